// round 1
// baseline (speedup 1.0000x reference)
#include <cuda_runtime.h>
#include <cstdint>

// Problem constants
#define T_SEQ   2048
#define DMODEL  1024
#define NHEAD   16
#define DHEAD   64
#define BATCH   2
#define MROWS   (BATCH * T_SEQ)   // 4096

// ---------------------------------------------------------------------------
// Scratch (allocation-free rule: __device__ globals)
// Q/K/V stored as [B, H, T, DH]; att output stored as [B*T, D]
// ---------------------------------------------------------------------------
__device__ float g_q[MROWS * DMODEL];
__device__ float g_k[MROWS * DMODEL];
__device__ float g_v[MROWS * DMODEL];
__device__ float g_att[MROWS * DMODEL];

// ---------------------------------------------------------------------------
// tf32 helpers
// ---------------------------------------------------------------------------
__device__ __forceinline__ float to_tf32(float x) {
    unsigned r;
    asm("cvt.rna.tf32.f32 %0, %1;" : "=r"(r) : "f"(x));
    return __uint_as_float(r);
}

// mma.sync m16n8k8 row.col f32 += tf32*tf32
// A frag: a0=(g,tg) a1=(g+8,tg) a2=(g,tg+4) a3=(g+8,tg+4)
// B frag: b0=(k=tg,n=g) b1=(k=tg+4,n=g)
// C frag: c0=(g,2tg) c1=(g,2tg+1) c2=(g+8,2tg) c3=(g+8,2tg+1)
__device__ __forceinline__ void mma_tf32(float* c, const float* a, const float* b) {
    asm volatile(
        "mma.sync.aligned.m16n8k8.row.col.f32.tf32.tf32.f32 "
        "{%0,%1,%2,%3}, {%4,%5,%6,%7}, {%8,%9}, {%0,%1,%2,%3};\n"
        : "+f"(c[0]), "+f"(c[1]), "+f"(c[2]), "+f"(c[3])
        : "r"(__float_as_uint(a[0])), "r"(__float_as_uint(a[1])),
          "r"(__float_as_uint(a[2])), "r"(__float_as_uint(a[3])),
          "r"(__float_as_uint(b[0])), "r"(__float_as_uint(b[1])));
}

// ---------------------------------------------------------------------------
// Generic tf32 GEMM:  C[4096,1024] = A[4096,1024] @ W[1024,1024]
// Block tile 128x128x32, 256 threads (8 warps as 2m x 4n, warp tile 64x32).
// src_sel: 0 -> Ain (x), 1 -> g_att
// dst_sel: 0/1/2 -> g_q/g_k/g_v with [B,H,T,DH] scatter; 3 -> Cout row-major
// ---------------------------------------------------------------------------
#define BM 128
#define BN 128
#define BK 32
#define ASTR 36    // (4g+tg)%32 distinct -> conflict-free A-frag reads
#define BSTR 136   // (8tg+g)%32 distinct -> conflict-free B-frag reads

__global__ __launch_bounds__(256, 1)
void gemm_tf32_kernel(const float* __restrict__ Ain,
                      const float* __restrict__ W,
                      float* __restrict__ Cout,
                      int src_sel, int dst_sel)
{
    __shared__ float As[BM * ASTR];
    __shared__ float Bs[BK * BSTR];

    const float* A = src_sel ? g_att : Ain;

    const int tid  = threadIdx.x;
    const int warp = tid >> 5, lane = tid & 31;
    const int g = lane >> 2, tg = lane & 3;
    const int wm = (warp & 1) * 64;   // 2 warps along M
    const int wn = (warp >> 1) * 32;  // 4 warps along N
    const int row0 = blockIdx.y * BM;
    const int col0 = blockIdx.x * BN;

    float acc[4][4][4];
#pragma unroll
    for (int mi = 0; mi < 4; mi++)
#pragma unroll
        for (int ni = 0; ni < 4; ni++)
#pragma unroll
            for (int i = 0; i < 4; i++) acc[mi][ni][i] = 0.f;

    const int arow = tid >> 3;        // 0..31
    const int acol = (tid & 7) * 4;   // 0..28
    const int brow = tid >> 5;        // 0..7
    const int bcol = (tid & 31) * 4;  // 0..124

    for (int kt = 0; kt < DMODEL; kt += BK) {
#pragma unroll
        for (int p = 0; p < 4; p++) {
            int r = arow + p * 32;
            float4 v = *(const float4*)&A[(size_t)(row0 + r) * DMODEL + kt + acol];
            float4 w; w.x = to_tf32(v.x); w.y = to_tf32(v.y);
            w.z = to_tf32(v.z); w.w = to_tf32(v.w);
            *(float4*)&As[r * ASTR + acol] = w;
        }
#pragma unroll
        for (int p = 0; p < 4; p++) {
            int r = brow + p * 8;
            float4 v = *(const float4*)&W[(size_t)(kt + r) * DMODEL + col0 + bcol];
            float4 w; w.x = to_tf32(v.x); w.y = to_tf32(v.y);
            w.z = to_tf32(v.z); w.w = to_tf32(v.w);
            *(float4*)&Bs[r * BSTR + bcol] = w;
        }
        __syncthreads();

#pragma unroll
        for (int ks = 0; ks < 4; ks++) {
            float a[4][4], b[4][2];
#pragma unroll
            for (int mi = 0; mi < 4; mi++) {
                int r = wm + mi * 16 + g;
                a[mi][0] = As[r * ASTR + ks * 8 + tg];
                a[mi][1] = As[(r + 8) * ASTR + ks * 8 + tg];
                a[mi][2] = As[r * ASTR + ks * 8 + tg + 4];
                a[mi][3] = As[(r + 8) * ASTR + ks * 8 + tg + 4];
            }
#pragma unroll
            for (int ni = 0; ni < 4; ni++) {
                int c = wn + ni * 8 + g;
                b[ni][0] = Bs[(ks * 8 + tg) * BSTR + c];
                b[ni][1] = Bs[(ks * 8 + tg + 4) * BSTR + c];
            }
#pragma unroll
            for (int mi = 0; mi < 4; mi++)
#pragma unroll
                for (int ni = 0; ni < 4; ni++)
                    mma_tf32(acc[mi][ni], a[mi], b[ni]);
        }
        __syncthreads();
    }

    // epilogue
    float* dsel = (dst_sel == 0) ? g_q : (dst_sel == 1) ? g_k : g_v;
#pragma unroll
    for (int mi = 0; mi < 4; mi++) {
#pragma unroll
        for (int ni = 0; ni < 4; ni++) {
#pragma unroll
            for (int i = 0; i < 4; i++) {
                int r = row0 + wm + mi * 16 + g + ((i >= 2) ? 8 : 0);
                int c = col0 + wn + ni * 8 + 2 * tg + (i & 1);
                float v = acc[mi][ni][i];
                if (dst_sel == 3) {
                    Cout[(size_t)r * DMODEL + c] = v;
                } else {
                    int bb = r >> 11, t = r & (T_SEQ - 1);
                    int hh = c >> 6, dh = c & (DHEAD - 1);
                    dsel[(((size_t)(bb * NHEAD + hh)) * T_SEQ + t) * DHEAD + dh] = v;
                }
            }
        }
    }
}

// ---------------------------------------------------------------------------
// Flash attention (causal), tf32 mma, fp32 online softmax.
// Block = (qtile of 64 rows, head, batch); 128 threads (4 warps x 16 q-rows).
// Dyn smem: Q[64][68], K[64][68], V[64][72], P[64][68]  = 70656 B
// Strides: Q/K/P stride 68 -> (4g+tg) banks; V stride 72 -> (8tg+g) banks.
// ---------------------------------------------------------------------------
#define QS 68
#define VS 72
#define ATTN_SMEM ((64 * QS * 3 + 64 * VS) * 4)

__global__ __launch_bounds__(128, 1)
void attn_kernel()
{
    extern __shared__ float sm[];
    float* Qs = sm;                 // 64*68
    float* Ks = Qs + 64 * QS;       // 64*68
    float* Vs = Ks + 64 * QS;       // 64*72
    float* Ps = Vs + 64 * VS;       // 64*68

    const int b = blockIdx.z, h = blockIdx.y, qt = blockIdx.x;
    const int q0 = qt * 64;
    const int bh = b * NHEAD + h;
    const float* qptr = g_q + (size_t)bh * T_SEQ * DHEAD;
    const float* kptr = g_k + (size_t)bh * T_SEQ * DHEAD;
    const float* vptr = g_v + (size_t)bh * T_SEQ * DHEAD;

    const int tid = threadIdx.x;
    const int warp = tid >> 5, lane = tid & 31;
    const int g = lane >> 2, tg = lane & 3;
    const int wm = warp * 16;

    // load Q tile (tf32-rounded)
    {
        const int col4 = (tid & 15) * 4;
        const int r0 = tid >> 4;
#pragma unroll
        for (int p = 0; p < 8; p++) {
            int r = r0 + p * 8;
            float4 v = *(const float4*)&qptr[(size_t)(q0 + r) * DHEAD + col4];
            float4 w; w.x = to_tf32(v.x); w.y = to_tf32(v.y);
            w.z = to_tf32(v.z); w.w = to_tf32(v.w);
            *(float4*)&Qs[r * QS + col4] = w;
        }
    }

    float o[8][4];
#pragma unroll
    for (int ni = 0; ni < 8; ni++)
#pragma unroll
        for (int i = 0; i < 4; i++) o[ni][i] = 0.f;
    float m0 = -1e30f, m1 = -1e30f, l0 = 0.f, l1 = 0.f;

    const int jmax = q0 / 64;           // causal: only tiles with keys <= q range
    const int qrow0 = q0 + wm + g;      // within-sequence query row (thread's row A)
    const int qrow1 = qrow0 + 8;        // row B

    for (int j = 0; j <= jmax; j++) {
        __syncthreads();
        // load K,V tiles
        {
            const int col4 = (tid & 15) * 4;
            const int r0 = tid >> 4;
#pragma unroll
            for (int p = 0; p < 8; p++) {
                int r = r0 + p * 8;
                float4 kv = *(const float4*)&kptr[(size_t)(j * 64 + r) * DHEAD + col4];
                float4 w; w.x = to_tf32(kv.x); w.y = to_tf32(kv.y);
                w.z = to_tf32(kv.z); w.w = to_tf32(kv.w);
                *(float4*)&Ks[r * QS + col4] = w;
                float4 vv = *(const float4*)&vptr[(size_t)(j * 64 + r) * DHEAD + col4];
                float4 w2; w2.x = to_tf32(vv.x); w2.y = to_tf32(vv.y);
                w2.z = to_tf32(vv.z); w2.w = to_tf32(vv.w);
                *(float4*)&Vs[r * VS + col4] = w2;
            }
        }
        __syncthreads();

        // S = Q @ K^T  (warp: 16 q-rows x 64 keys)
        float s[8][4];
#pragma unroll
        for (int ni = 0; ni < 8; ni++)
#pragma unroll
            for (int i = 0; i < 4; i++) s[ni][i] = 0.f;

#pragma unroll
        for (int ks = 0; ks < 8; ks++) {
            float a[4];
            a[0] = Qs[(wm + g) * QS + ks * 8 + tg];
            a[1] = Qs[(wm + g + 8) * QS + ks * 8 + tg];
            a[2] = Qs[(wm + g) * QS + ks * 8 + tg + 4];
            a[3] = Qs[(wm + g + 8) * QS + ks * 8 + tg + 4];
#pragma unroll
            for (int ni = 0; ni < 8; ni++) {
                float bf[2];
                bf[0] = Ks[(ni * 8 + g) * QS + ks * 8 + tg];
                bf[1] = Ks[(ni * 8 + g) * QS + ks * 8 + tg + 4];
                mma_tf32(s[ni], a, bf);
            }
        }

        // scale + causal mask
        const float scale = 0.125f;  // 1/sqrt(64)
#pragma unroll
        for (int ni = 0; ni < 8; ni++) {
            int kc = j * 64 + ni * 8 + 2 * tg;
            s[ni][0] = (kc     > qrow0) ? -1e30f : s[ni][0] * scale;
            s[ni][1] = (kc + 1 > qrow0) ? -1e30f : s[ni][1] * scale;
            s[ni][2] = (kc     > qrow1) ? -1e30f : s[ni][2] * scale;
            s[ni][3] = (kc + 1 > qrow1) ? -1e30f : s[ni][3] * scale;
        }

        // online softmax: rowmax over 4 lanes sharing a row (xor 1,2)
        float mx0 = -1e30f, mx1 = -1e30f;
#pragma unroll
        for (int ni = 0; ni < 8; ni++) {
            mx0 = fmaxf(mx0, fmaxf(s[ni][0], s[ni][1]));
            mx1 = fmaxf(mx1, fmaxf(s[ni][2], s[ni][3]));
        }
        mx0 = fmaxf(mx0, __shfl_xor_sync(0xffffffffu, mx0, 1));
        mx0 = fmaxf(mx0, __shfl_xor_sync(0xffffffffu, mx0, 2));
        mx1 = fmaxf(mx1, __shfl_xor_sync(0xffffffffu, mx1, 1));
        mx1 = fmaxf(mx1, __shfl_xor_sync(0xffffffffu, mx1, 2));

        float mn0 = fmaxf(m0, mx0), mn1 = fmaxf(m1, mx1);
        float al0 = __expf(m0 - mn0), al1 = __expf(m1 - mn1);
        m0 = mn0; m1 = mn1;

        float sum0 = 0.f, sum1 = 0.f;
#pragma unroll
        for (int ni = 0; ni < 8; ni++) {
            float p00 = __expf(s[ni][0] - m0), p01 = __expf(s[ni][1] - m0);
            float p10 = __expf(s[ni][2] - m1), p11 = __expf(s[ni][3] - m1);
            sum0 += p00 + p01; sum1 += p10 + p11;
            Ps[(wm + g) * QS + ni * 8 + 2 * tg]         = to_tf32(p00);
            Ps[(wm + g) * QS + ni * 8 + 2 * tg + 1]     = to_tf32(p01);
            Ps[(wm + g + 8) * QS + ni * 8 + 2 * tg]     = to_tf32(p10);
            Ps[(wm + g + 8) * QS + ni * 8 + 2 * tg + 1] = to_tf32(p11);
        }
        sum0 += __shfl_xor_sync(0xffffffffu, sum0, 1);
        sum0 += __shfl_xor_sync(0xffffffffu, sum0, 2);
        sum1 += __shfl_xor_sync(0xffffffffu, sum1, 1);
        sum1 += __shfl_xor_sync(0xffffffffu, sum1, 2);
        l0 = l0 * al0 + sum0;
        l1 = l1 * al1 + sum1;

        // rescale O accumulators (rows g -> c0/c1, g+8 -> c2/c3)
#pragma unroll
        for (int ni = 0; ni < 8; ni++) {
            o[ni][0] *= al0; o[ni][1] *= al0;
            o[ni][2] *= al1; o[ni][3] *= al1;
        }
        __syncwarp();   // P smem visible within warp (warp-private rows)

        // O += P @ V
#pragma unroll
        for (int ks = 0; ks < 8; ks++) {
            float a[4];
            a[0] = Ps[(wm + g) * QS + ks * 8 + tg];
            a[1] = Ps[(wm + g + 8) * QS + ks * 8 + tg];
            a[2] = Ps[(wm + g) * QS + ks * 8 + tg + 4];
            a[3] = Ps[(wm + g + 8) * QS + ks * 8 + tg + 4];
#pragma unroll
            for (int ni = 0; ni < 8; ni++) {
                float bf[2];
                bf[0] = Vs[(ks * 8 + tg) * VS + ni * 8 + g];
                bf[1] = Vs[(ks * 8 + tg + 4) * VS + ni * 8 + g];
                mma_tf32(o[ni], a, bf);
            }
        }
    }

    // epilogue: normalize and scatter to [B*T, D] layout
    const float inv0 = 1.f / l0, inv1 = 1.f / l1;
#pragma unroll
    for (int ni = 0; ni < 8; ni++) {
        int c = h * DHEAD + ni * 8 + 2 * tg;
        g_att[((size_t)b * T_SEQ + qrow0) * DMODEL + c]     = o[ni][0] * inv0;
        g_att[((size_t)b * T_SEQ + qrow0) * DMODEL + c + 1] = o[ni][1] * inv0;
        g_att[((size_t)b * T_SEQ + qrow1) * DMODEL + c]     = o[ni][2] * inv1;
        g_att[((size_t)b * T_SEQ + qrow1) * DMODEL + c + 1] = o[ni][3] * inv1;
    }
}

// ---------------------------------------------------------------------------
// kernel_launch: x, mask(ignored; causal is hard-coded), Wq, Wk, Wv, Wo
// ---------------------------------------------------------------------------
extern "C" void kernel_launch(void* const* d_in, const int* in_sizes, int n_in,
                              void* d_out, int out_size)
{
    (void)in_sizes; (void)n_in; (void)out_size;
    const float* x  = (const float*)d_in[0];
    const float* Wq = (const float*)d_in[2];
    const float* Wk = (const float*)d_in[3];
    const float* Wv = (const float*)d_in[4];
    const float* Wo = (const float*)d_in[5];
    float* out = (float*)d_out;

    dim3 gg(DMODEL / BN, MROWS / BM);   // (8, 32)
    gemm_tf32_kernel<<<gg, 256>>>(x, Wq, nullptr, 0, 0);
    gemm_tf32_kernel<<<gg, 256>>>(x, Wk, nullptr, 0, 1);
    gemm_tf32_kernel<<<gg, 256>>>(x, Wv, nullptr, 0, 2);

    cudaFuncSetAttribute(attn_kernel,
                         cudaFuncAttributeMaxDynamicSharedMemorySize, ATTN_SMEM);
    dim3 ga(T_SEQ / 64, NHEAD, BATCH);  // (32, 16, 2)
    attn_kernel<<<ga, 128, ATTN_SMEM>>>();

    gemm_tf32_kernel<<<gg, 256>>>(nullptr, Wo, out, 1, 3);
}